// round 16
// baseline (speedup 1.0000x reference)
#include <cuda_runtime.h>
#include <cuda_fp16.h>
#include <cstdint>

// Problem constants
#define BN 8
#define CCH 128
#define HH 128
#define WW 256
#define NI 65

// Tiling
#define WT 64
#define KC 32
#define LDA 72      // X1s stride in halves
#define LDB 136     // X2s stride in halves
#define LDJ 68      // cs2 stride in floats (272B = 17*16)
#define JROWS 80    // idx=(j+15) wrapped mod 80; valid j -> [15,79]

#define X1BUF (KC * LDA)
#define X2BUF (KC * LDB)

#define NCONS 256                      // 8 consumer warps (MMA + epilogue)
#define NTHREADS 320                   // + 2 producer warps (LDG/cvt/STS only)
#define GRIDX 456                      // 152 SMs x 3 resident CTAs (persistent)
#define NTILES (BN * HH * (WW / WT))   // 4096
#define CSTRIDE ((size_t)HH * WW)

// named barriers (id 0 reserved for __syncthreads; unused here)
#define BFULL(b)  (1 + (b))
#define BEMPTY(b) (3 + (b))
#define BCONS     5

__device__ __forceinline__ void bar_sync(int id, int cnt) {
    asm volatile("bar.sync %0, %1;" :: "r"(id), "r"(cnt) : "memory");
}
__device__ __forceinline__ void bar_arrive(int id, int cnt) {
    asm volatile("bar.arrive %0, %1;" :: "r"(id), "r"(cnt) : "memory");
}

__global__ __launch_bounds__(NTHREADS, 3)
void corr_volume_kernel(const float* __restrict__ x1,
                        const float* __restrict__ x2,
                        float* __restrict__ out)
{
    __shared__ __align__(16) __half X1s[2][X1BUF];     //  9216 B
    __shared__ __align__(16) __half X2s[2][X2BUF];     // 17408 B
    __shared__ __align__(16) float  cs2[JROWS * LDJ];  // 21760 B (48384 static)

    const int tid = threadIdx.x;

    if (tid >= NCONS) {
        // ================= producer warps (tid 256..319) =================
        const int ptid = tid - NCONS;       // 0..63
        const int ar   = ptid >> 4;         // A row base 0..3
        const int ac4  = (ptid & 15) * 4;   // A col (floats)
        const int br   = ptid >> 5;         // B row base 0..1
        const int bc4  = (ptid & 31) * 4;   // B col (floats)
        const bool bsafe = (bc4 >= 64);

        int g = 0;
        for (int t = blockIdx.x; t < NTILES; t += GRIDX) {
            const int bx = t & 3, h = (t >> 2) & (HH - 1), n = t >> 9;
            const float* pA = x1 + ((size_t)n * CCH * HH + (size_t)h) * WW + bx * WT
                              + (size_t)ar * CSTRIDE + ac4;
            const float* pB = x2 + ((size_t)n * CCH * HH + (size_t)h) * WW + (bx * WT - 64)
                              + (size_t)br * CSTRIDE + bc4;
            const bool okB = (bx != 0) || bsafe;

            for (int kc = 0; kc < 4; kc++, g++) {
                const int b = g & 1;
                if (g >= 2) bar_sync(BEMPTY(b), NTHREADS);

                // A chunk: 32 rows x 64 floats -> 8 float4/thread
                {
                    float4 v[8];
                    #pragma unroll
                    for (int i = 0; i < 8; i++)
                        v[i] = *(const float4*)(pA + (size_t)(kc * KC + i * 4) * CSTRIDE);
                    #pragma unroll
                    for (int i = 0; i < 8; i++) {
                        __half2* d = (__half2*)&X1s[b][(ar + i * 4) * LDA + ac4];
                        d[0] = __floats2half2_rn(v[i].x, v[i].y);
                        d[1] = __floats2half2_rn(v[i].z, v[i].w);
                    }
                }
                // B chunk: 32 rows x 128 floats -> 16 float4/thread, two batches
                #pragma unroll
                for (int hb = 0; hb < 2; hb++) {
                    float4 v[8];
                    #pragma unroll
                    for (int i = 0; i < 8; i++) {
                        if (okB)
                            v[i] = *(const float4*)(pB +
                                (size_t)(kc * KC + (hb * 8 + i) * 2) * CSTRIDE);
                        else
                            v[i] = make_float4(0.f, 0.f, 0.f, 0.f);
                    }
                    #pragma unroll
                    for (int i = 0; i < 8; i++) {
                        int row = br + (hb * 8 + i) * 2;
                        __half2* d = (__half2*)&X2s[b][row * LDB + bc4];
                        d[0] = __floats2half2_rn(v[i].x, v[i].y);
                        d[1] = __floats2half2_rn(v[i].z, v[i].w);
                    }
                }
                bar_arrive(BFULL(b), NTHREADS);
            }
        }
        return;
    }

    // ================= consumer warps (tid 0..255) =================
    const int lane = tid & 31;
    const int wid  = tid >> 5;
    const int wm   = wid >> 1;
    const int wn   = wid & 1;
    const int m0   = wm * 16;
    const int nst  = m0 + wn * 40;

    const uint32_t x1s_base = (uint32_t)__cvta_generic_to_shared(X1s);
    const uint32_t x2s_base = (uint32_t)__cvta_generic_to_shared(X2s);
    const int r = lane & 7;
    const uint32_t addrA0 = x1s_base +
        2u * ((uint32_t)((r + ((lane >> 4) & 1) * 8) * LDA + (m0 + ((lane >> 3) & 1) * 8)));
    const uint32_t addrB0 = x2s_base +
        2u * ((uint32_t)((r + ((lane >> 3) & 1) * 8) * LDB + (nst + ((lane >> 4) & 1) * 8)));

    float acc[5][4];

    auto mma_phase = [&](int buf) {
        const uint32_t offA = (uint32_t)(buf * X1BUF * 2);
        const uint32_t offB = (uint32_t)(buf * X2BUF * 2);
        #pragma unroll
        for (int ks = 0; ks < KC / 16; ks++) {
            uint32_t a[4];
            {
                uint32_t aaddr = addrA0 + offA + 2u * (uint32_t)(ks * 16 * LDA);
                asm volatile(
                    "ldmatrix.sync.aligned.m8n8.x4.trans.shared.b16 {%0,%1,%2,%3}, [%4];\n"
                    : "=r"(a[0]), "=r"(a[1]), "=r"(a[2]), "=r"(a[3]) : "r"(aaddr));
            }
            #pragma unroll
            for (int p = 0; p < 2; p++) {
                uint32_t b0, b1, b2, b3;
                uint32_t baddr = addrB0 + offB + 2u * (uint32_t)(ks * 16 * LDB + p * 16);
                asm volatile(
                    "ldmatrix.sync.aligned.m8n8.x4.trans.shared.b16 {%0,%1,%2,%3}, [%4];\n"
                    : "=r"(b0), "=r"(b1), "=r"(b2), "=r"(b3) : "r"(baddr));
                asm volatile(
                    "mma.sync.aligned.m16n8k16.row.col.f32.f16.f16.f32 "
                    "{%0,%1,%2,%3}, {%4,%5,%6,%7}, {%8,%9}, {%0,%1,%2,%3};\n"
                    : "+f"(acc[2*p][0]), "+f"(acc[2*p][1]), "+f"(acc[2*p][2]), "+f"(acc[2*p][3])
                    : "r"(a[0]), "r"(a[1]), "r"(a[2]), "r"(a[3]), "r"(b0), "r"(b1));
                asm volatile(
                    "mma.sync.aligned.m16n8k16.row.col.f32.f16.f16.f32 "
                    "{%0,%1,%2,%3}, {%4,%5,%6,%7}, {%8,%9}, {%0,%1,%2,%3};\n"
                    : "+f"(acc[2*p+1][0]), "+f"(acc[2*p+1][1]), "+f"(acc[2*p+1][2]), "+f"(acc[2*p+1][3])
                    : "r"(a[0]), "r"(a[1]), "r"(a[2]), "r"(a[3]), "r"(b2), "r"(b3));
            }
            {
                uint32_t b0, b1;
                uint32_t baddr = addrB0 + offB + 2u * (uint32_t)(ks * 16 * LDB + 32);
                asm volatile(
                    "ldmatrix.sync.aligned.m8n8.x2.trans.shared.b16 {%0,%1}, [%2];\n"
                    : "=r"(b0), "=r"(b1) : "r"(baddr));
                asm volatile(
                    "mma.sync.aligned.m16n8k16.row.col.f32.f16.f16.f32 "
                    "{%0,%1,%2,%3}, {%4,%5,%6,%7}, {%8,%9}, {%0,%1,%2,%3};\n"
                    : "+f"(acc[4][0]), "+f"(acc[4][1]), "+f"(acc[4][2]), "+f"(acc[4][3])
                    : "r"(a[0]), "r"(a[1]), "r"(a[2]), "r"(a[3]), "r"(b0), "r"(b1));
            }
        }
    };

    for (int t = blockIdx.x; t < NTILES; t += GRIDX) {
        #pragma unroll
        for (int i5 = 0; i5 < 5; i5++)
            #pragma unroll
            for (int j = 0; j < 4; j++) acc[i5][j] = 0.f;

        // consume 4 chunks; producers refill freed buffers immediately,
        // including while we run the epilogue below.
        #pragma unroll
        for (int kc = 0; kc < 4; kc++) {
            const int b = kc & 1;
            bar_sync(BFULL(b), NTHREADS);
            mma_phase(b);
            bar_arrive(BEMPTY(b), NTHREADS);
        }

        // band staging (per-warp private writes)
        {
            const int rowa = m0 + (lane >> 2);
            #pragma unroll
            for (int t8 = 0; t8 < 5; t8++) {
                int colb = nst + t8 * 8 + 2 * (lane & 3);
                int j0 = colb - rowa + 15;
                int ja = j0;     if (ja >= JROWS) ja -= JROWS;
                int jb = j0 + 1; if (jb >= JROWS) jb -= JROWS;
                int jc = j0 - 8; if (jc >= JROWS) jc -= JROWS;
                int jd = j0 - 7; if (jd >= JROWS) jd -= JROWS;
                cs2[ja * LDJ + rowa]     = acc[t8][0];
                cs2[jb * LDJ + rowa]     = acc[t8][1];
                cs2[jc * LDJ + rowa + 8] = acc[t8][2];
                cs2[jd * LDJ + rowa + 8] = acc[t8][3];
            }
        }
        bar_sync(BCONS, NCONS);   // staging visible to all consumer warps

        // vectorized de-band output (streaming stores)
        {
            const int bx = t & 3, h = (t >> 2) & (HH - 1), n = t >> 9;
            const int q    = tid & 15;
            const int rowi = tid >> 4;
            float* ob = out + (((size_t)n * NI) * HH + h) * WW + bx * WT + 4 * q;
            #pragma unroll
            for (int it = 0; it < 5; it++) {
                int i = it * 16 + rowi;
                if (i < NI) {
                    float4 v = *(const float4*)(cs2 + (79 - i) * LDJ + 4 * q);
                    v.x *= (1.0f / 128.0f); v.y *= (1.0f / 128.0f);
                    v.z *= (1.0f / 128.0f); v.w *= (1.0f / 128.0f);
                    __stcs((float4*)(ob + (size_t)i * HH * WW), v);
                }
            }
        }
        bar_sync(BCONS, NCONS);   // output reads done before next tile's staging
    }
}

extern "C" void kernel_launch(void* const* d_in, const int* in_sizes, int n_in,
                              void* d_out, int out_size)
{
    const float* x1 = (const float*)d_in[0];
    const float* x2 = (const float*)d_in[1];
    float* out = (float*)d_out;
    (void)in_sizes; (void)n_in; (void)out_size;

    dim3 grid(GRIDX);
    dim3 block(NTHREADS);
    corr_volume_kernel<<<grid, block>>>(x1, x2, out);
}

// round 17
// speedup vs baseline: 1.5337x; 1.5337x over previous
#include <cuda_runtime.h>
#include <cuda_fp16.h>
#include <cstdint>

// Problem constants
#define BN 8
#define CCH 128
#define HH 128
#define WW 256
#define NI 65

// Tiling
#define WT 64
#define KC 32
#define LDA 72      // X1s stride in halves
#define LDB 136     // X2s stride in halves
#define LDJ 68      // cs2 stride in floats (272B = 17*16)
#define JROWS 80    // idx=(j+15) wrapped mod 80; valid j -> [15,79]

#define X1BUF (KC * LDA)
#define X2BUF (KC * LDB)

#define GRIDX 608                      // 152 SMs x 4 resident CTAs (GB300!)
#define NTILES (BN * HH * (WW / WT))   // 4096
#define CSTRIDE ((size_t)HH * WW)

__global__ __launch_bounds__(256, 4)
void corr_volume_kernel(const float* __restrict__ x1,
                        const float* __restrict__ x2,
                        float* __restrict__ out)
{
    __shared__ __align__(16) __half X1s[2][X1BUF];     //  9216 B
    __shared__ __align__(16) __half X2s[2][X2BUF];     // 17408 B
    __shared__ __align__(16) float  cs2[JROWS * LDJ];  // 21760 B (48384 total, STATIC)

    const int tid  = threadIdx.x;
    const int lane = tid & 31;
    const int wid  = tid >> 5;
    const int wm   = wid >> 1;
    const int wn   = wid & 1;
    const int m0   = wm * 16;
    const int nst  = m0 + wn * 40;

    const uint32_t x1s_base = (uint32_t)__cvta_generic_to_shared(X1s);
    const uint32_t x2s_base = (uint32_t)__cvta_generic_to_shared(X2s);
    const int r = lane & 7;
    const uint32_t addrA0 = x1s_base +
        2u * ((uint32_t)((r + ((lane >> 4) & 1) * 8) * LDA + (m0 + ((lane >> 3) & 1) * 8)));
    const uint32_t addrB0 = x2s_base +
        2u * ((uint32_t)((r + ((lane >> 3) & 1) * 8) * LDB + (nst + ((lane >> 4) & 1) * 8)));

    // fixed per-thread load coordinates
    const int cr1a = tid >> 4;
    const int co1  = (tid & 15) * 4;
    const int cr2a = tid >> 5;
    const int co2  = (tid & 31) * 4;

    float acc[5][4];
    float4 p1[2], p2[4];

    auto tile_pA = [&](int t) -> const float* {
        int bx = t & 3, h = (t >> 2) & (HH - 1), n = t >> 9;
        return x1 + ((size_t)n * CCH * HH + (size_t)h) * WW + bx * WT
                  + (size_t)cr1a * CSTRIDE + co1;
    };
    auto tile_pB = [&](int t) -> const float* {
        int bx = t & 3, h = (t >> 2) & (HH - 1), n = t >> 9;
        return x2 + ((size_t)n * CCH * HH + (size_t)h) * WW + (bx * WT - 64)
                  + (size_t)cr2a * CSTRIDE + co2;
    };

    auto load_chunk = [&](const float* pA, const float* pB, bool ok, int kc) {
        #pragma unroll
        for (int it = 0; it < 2; it++)
            p1[it] = *(const float4*)(pA + (size_t)(kc * KC + it * 16) * CSTRIDE);
        #pragma unroll
        for (int it = 0; it < 4; it++) {
            if (ok)
                p2[it] = *(const float4*)(pB + (size_t)(kc * KC + it * 8) * CSTRIDE);
            else
                p2[it] = make_float4(0.f, 0.f, 0.f, 0.f);
        }
    };
    auto store_chunk = [&](int buf) {
        #pragma unroll
        for (int it = 0; it < 2; it++) {
            __half2* d = (__half2*)&X1s[buf][(cr1a + it * 16) * LDA + co1];
            d[0] = __floats2half2_rn(p1[it].x, p1[it].y);
            d[1] = __floats2half2_rn(p1[it].z, p1[it].w);
        }
        #pragma unroll
        for (int it = 0; it < 4; it++) {
            __half2* d = (__half2*)&X2s[buf][(cr2a + it * 8) * LDB + co2];
            d[0] = __floats2half2_rn(p2[it].x, p2[it].y);
            d[1] = __floats2half2_rn(p2[it].z, p2[it].w);
        }
    };

    auto mma_phase = [&](int buf) {
        const uint32_t offA = (uint32_t)(buf * X1BUF * 2);
        const uint32_t offB = (uint32_t)(buf * X2BUF * 2);
        #pragma unroll
        for (int ks = 0; ks < KC / 16; ks++) {
            uint32_t a[4];
            {
                uint32_t aaddr = addrA0 + offA + 2u * (uint32_t)(ks * 16 * LDA);
                asm volatile(
                    "ldmatrix.sync.aligned.m8n8.x4.trans.shared.b16 {%0,%1,%2,%3}, [%4];\n"
                    : "=r"(a[0]), "=r"(a[1]), "=r"(a[2]), "=r"(a[3]) : "r"(aaddr));
            }
            #pragma unroll
            for (int p = 0; p < 2; p++) {
                uint32_t b0, b1, b2, b3;
                uint32_t baddr = addrB0 + offB + 2u * (uint32_t)(ks * 16 * LDB + p * 16);
                asm volatile(
                    "ldmatrix.sync.aligned.m8n8.x4.trans.shared.b16 {%0,%1,%2,%3}, [%4];\n"
                    : "=r"(b0), "=r"(b1), "=r"(b2), "=r"(b3) : "r"(baddr));
                asm volatile(
                    "mma.sync.aligned.m16n8k16.row.col.f32.f16.f16.f32 "
                    "{%0,%1,%2,%3}, {%4,%5,%6,%7}, {%8,%9}, {%0,%1,%2,%3};\n"
                    : "+f"(acc[2*p][0]), "+f"(acc[2*p][1]), "+f"(acc[2*p][2]), "+f"(acc[2*p][3])
                    : "r"(a[0]), "r"(a[1]), "r"(a[2]), "r"(a[3]), "r"(b0), "r"(b1));
                asm volatile(
                    "mma.sync.aligned.m16n8k16.row.col.f32.f16.f16.f32 "
                    "{%0,%1,%2,%3}, {%4,%5,%6,%7}, {%8,%9}, {%0,%1,%2,%3};\n"
                    : "+f"(acc[2*p+1][0]), "+f"(acc[2*p+1][1]), "+f"(acc[2*p+1][2]), "+f"(acc[2*p+1][3])
                    : "r"(a[0]), "r"(a[1]), "r"(a[2]), "r"(a[3]), "r"(b2), "r"(b3));
            }
            {
                uint32_t b0, b1;
                uint32_t baddr = addrB0 + offB + 2u * (uint32_t)(ks * 16 * LDB + 32);
                asm volatile(
                    "ldmatrix.sync.aligned.m8n8.x2.trans.shared.b16 {%0,%1}, [%2];\n"
                    : "=r"(b0), "=r"(b1) : "r"(baddr));
                asm volatile(
                    "mma.sync.aligned.m16n8k16.row.col.f32.f16.f16.f32 "
                    "{%0,%1,%2,%3}, {%4,%5,%6,%7}, {%8,%9}, {%0,%1,%2,%3};\n"
                    : "+f"(acc[4][0]), "+f"(acc[4][1]), "+f"(acc[4][2]), "+f"(acc[4][3])
                    : "r"(a[0]), "r"(a[1]), "r"(a[2]), "r"(a[3]), "r"(b0), "r"(b1));
            }
        }
    };

    int t = blockIdx.x;
    if (t >= NTILES) return;

    const float* pA = tile_pA(t);
    const float* pB = tile_pB(t);
    bool ok = ((t & 3) != 0) || (co2 >= 64);

    // prologue: c0 -> b0; sync; THEN load c1 (no barrier between load and kc0 store)
    load_chunk(pA, pB, ok, 0);
    store_chunk(0);
    __syncthreads();
    load_chunk(pA, pB, ok, 1);

    while (true) {
        const int tn = t + GRIDX;
        const bool has_next = (tn < NTILES);

        #pragma unroll
        for (int i5 = 0; i5 < 5; i5++)
            #pragma unroll
            for (int j = 0; j < 4; j++) acc[i5][j] = 0.f;

        // kc0: MMA b0 (c0); store c1 -> b1. (c1 LDGs issued after last barrier.)
        mma_phase(0);
        store_chunk(1);
        __syncthreads();

        // kc1: load c2; MMA b1 (c1); store c2 -> b0.
        load_chunk(pA, pB, ok, 2);
        mma_phase(1);
        store_chunk(0);
        __syncthreads();

        // kc2: load c3; MMA b0 (c2); store c3 -> b1.
        load_chunk(pA, pB, ok, 3);
        mma_phase(0);
        store_chunk(1);
        __syncthreads();

        // kc3: load next-c0; MMA b1 (c3); store next-c0 -> b0.
        const float* pAN = has_next ? tile_pA(tn) : pA;
        const float* pBN = has_next ? tile_pB(tn) : pB;
        const bool okN = has_next ? (((tn & 3) != 0) || (co2 >= 64)) : false;
        if (has_next)
            load_chunk(pAN, pBN, okN, 0);
        mma_phase(1);
        if (has_next)
            store_chunk(0);

        // band staging (per-warp private writes; precedes the single barrier)
        {
            const int rowa = m0 + (lane >> 2);
            #pragma unroll
            for (int t8 = 0; t8 < 5; t8++) {
                int colb = nst + t8 * 8 + 2 * (lane & 3);
                int j0 = colb - rowa + 15;
                int ja = j0;     if (ja >= JROWS) ja -= JROWS;
                int jb = j0 + 1; if (jb >= JROWS) jb -= JROWS;
                int jc = j0 - 8; if (jc >= JROWS) jc -= JROWS;
                int jd = j0 - 7; if (jd >= JROWS) jd -= JROWS;
                cs2[ja * LDJ + rowa]     = acc[t8][0];
                cs2[jb * LDJ + rowa]     = acc[t8][1];
                cs2[jc * LDJ + rowa + 8] = acc[t8][2];
                cs2[jd * LDJ + rowa + 8] = acc[t8][3];
            }
        }

        __syncthreads();   // staging visible; fences b0 store

        // prefetch next tile's c1 AFTER the barrier: LDGs in flight during output
        // STGs and next kc0's MMA; consumed at kc0's store with no barrier crossed.
        if (has_next)
            load_chunk(pAN, pBN, okN, 1);

        // vectorized de-band output (streaming stores; out never re-read)
        {
            const int bx = t & 3, h = (t >> 2) & (HH - 1), n = t >> 9;
            const int q    = tid & 15;
            const int rowi = tid >> 4;
            float* ob = out + (((size_t)n * NI) * HH + h) * WW + bx * WT + 4 * q;
            #pragma unroll
            for (int it = 0; it < 5; it++) {
                int i = it * 16 + rowi;
                if (i < NI) {
                    float4 v = *(const float4*)(cs2 + (79 - i) * LDJ + 4 * q);
                    v.x *= (1.0f / 128.0f); v.y *= (1.0f / 128.0f);
                    v.z *= (1.0f / 128.0f); v.w *= (1.0f / 128.0f);
                    __stcs((float4*)(ob + (size_t)i * HH * WW), v);
                }
            }
        }
        // cs2 reads complete before next staging (3 chunk syncs away)

        if (!has_next) break;
        t = tn;
        pA = pAN; pB = pBN; ok = okN;
    }
}

extern "C" void kernel_launch(void* const* d_in, const int* in_sizes, int n_in,
                              void* d_out, int out_size)
{
    const float* x1 = (const float*)d_in[0];
    const float* x2 = (const float*)d_in[1];
    float* out = (float*)d_out;
    (void)in_sizes; (void)n_in; (void)out_size;

    dim3 grid(GRIDX);
    dim3 block(256);
    corr_volume_kernel<<<grid, block>>>(x1, x2, out);
}